// round 8
// baseline (speedup 1.0000x reference)
#include <cuda_runtime.h>
#include <cstdint>

// MTF_68461778698457: Markov Transition Field
// x: (N=4096, C=4, L=256) f32  ->  out: (N, C, 65, 65) f32
//
// One WARP per row (8 elems/thread register bitonic sort), 8 rows per CTA.
// Phase 2 is warp-local: zero-fill output, per-warp u8 histogram with
// match_any dedup (no atomics -> deterministic, bit-exact), scatter-store
// only touched bins.
//
// Numerics (locked, rel_err == 0.0): reference division == classical
// div.full.f32 Newton expansion; we hoist the refined reciprocal r1(b) and
// mul.rn — bit-identical to div.full(a,b).

constexpr int L    = 256;
constexpr int NB   = 65;
constexpr int NB2  = NB * NB;        // 4225
constexpr int RPC  = 8;              // rows per CTA (one per warp)
constexpr int HPAD = 4352;           // u8 hist row (4225 + pad, 16B multiple)
constexpr int SENT = 4300;           // sentinel code for invalid transitions

__device__ __forceinline__ float refined_rcp(float b)
{
    float r;
    asm("{\n\t"
        ".reg .f32 r0, e;\n\t"
        "rcp.approx.f32 r0, %1;\n\t"
        "fma.rn.f32 e, %1, r0, 0fBF800000;\n\t"   // e' = b*r0 - 1
        "neg.f32 e, e;\n\t"                        // e  = 1 - b*r0
        "fma.rn.f32 %0, r0, e, r0;\n\t"            // r1 = r0 + r0*e
        "}"
        : "=f"(r) : "f"(b));
    return r;
}

__global__ __launch_bounds__(256)
void mtf_kernel(const float* __restrict__ x, float* __restrict__ out)
{
    __shared__ __align__(16) unsigned char shist[RPC][HPAD];  // 34.8 KB
    __shared__ __align__(16) unsigned char sbin[RPC][272];    //  2.2 KB

    const int t    = threadIdx.x;
    const int w    = t >> 5;
    const int lane = t & 31;
    const long long rowg = (long long)blockIdx.x * RPC + w;

    // ---- CTA-cooperative zero-fill of this CTA's 8 output rows ------------
    // 8*4225 = 33800 floats, base offset 33800*bid -> 16B aligned, 8450 f4.
    {
        float4* ob = (float4*)(out + (size_t)blockIdx.x * (RPC * NB2));
        const float4 z = make_float4(0.f, 0.f, 0.f, 0.f);
        for (int i = t; i < (RPC * NB2) / 4; i += 256) ob[i] = z;
    }

    // ---- zero this warp's u8 histogram (per-warp private) -----------------
    {
        uint4* h4 = (uint4*)shist[w];
        const uint4 z = make_uint4(0u, 0u, 0u, 0u);
        #pragma unroll
        for (int i = lane; i < HPAD / 16; i += 32) h4[i] = z;
    }

    // ---- Phase 1: load, range scan, register bitonic sort ------------------
    const float* xr = x + rowg * L + lane * 8;
    float4 va = *(const float4*)(xr);
    float4 vb = *(const float4*)(xr + 4);
    float v[8] = { va.x, va.y, va.z, va.w, vb.x, vb.y, vb.z, vb.w };

    int locF = 256, locE = -1;
    #pragma unroll
    for (int i = 0; i < 8; i++) {
        int idx = lane * 8 + i;
        if (v[i] != 0.0f) {
            if (idx < locF) locF = idx;
            if (idx > locE) locE = idx;
        }
    }
    const int first = __reduce_min_sync(0xffffffffu, locF);
    const int last  = __reduce_max_sync(0xffffffffu, locE);
    const bool has  = (last >= first);
    const int  vl   = has ? (last - first + 1) : 1;

    unsigned long long key[8];
    #pragma unroll
    for (int i = 0; i < 8; i++) {
        int idx = lane * 8 + i;
        unsigned int u = __float_as_uint(v[i]);
        unsigned int o = (u & 0x80000000u) ? ~u : (u | 0x80000000u);
        bool valid = has && (idx >= first) && (idx <= last);
        key[i] = valid ? ((((unsigned long long)o) << 32) | (unsigned)idx)
                       : 0xFFFFFFFFFFFFFFFFull;
    }

    #define CE(a, b, asc)                                                    \
        do {                                                                 \
            if ((key[a] > key[b]) == (asc)) {                                \
                unsigned long long _tmp = key[a];                            \
                key[a] = key[b]; key[b] = _tmp;                              \
            }                                                                \
        } while (0)

    #define STAGE_SHFL(off, asc)                                             \
        do {                                                                 \
            bool _lower = (lane & (off)) == 0;                               \
            bool _keepMin = ((asc) == _lower);                               \
            _Pragma("unroll")                                                \
            for (int _i = 0; _i < 8; _i++) {                                 \
                unsigned long long _o =                                      \
                    __shfl_xor_sync(0xffffffffu, key[_i], (off));            \
                bool _take = (_o < key[_i]) == _keepMin;                     \
                key[_i] = _take ? _o : key[_i];                              \
            }                                                                \
        } while (0)

    #define LOCAL3(asc)                                                      \
        do {                                                                 \
            CE(0,4,asc); CE(1,5,asc); CE(2,6,asc); CE(3,7,asc);              \
            CE(0,2,asc); CE(1,3,asc); CE(4,6,asc); CE(5,7,asc);              \
            CE(0,1,asc); CE(2,3,asc); CE(4,5,asc); CE(6,7,asc);              \
        } while (0)

    CE(0,1,true); CE(2,3,false); CE(4,5,true); CE(6,7,false);
    CE(0,2,true); CE(1,3,true);  CE(4,6,false); CE(5,7,false);
    CE(0,1,true); CE(2,3,true);  CE(4,5,false); CE(6,7,false);
    { bool a = (lane & 1) == 0; LOCAL3(a); }
    { bool a = (lane & 2) == 0; STAGE_SHFL(1, a); LOCAL3(a); }
    { bool a = (lane & 4) == 0; STAGE_SHFL(2, a); STAGE_SHFL(1, a); LOCAL3(a); }
    { bool a = (lane & 8) == 0; STAGE_SHFL(4, a); STAGE_SHFL(2, a);
      STAGE_SHFL(1, a); LOCAL3(a); }
    { bool a = (lane & 16) == 0; STAGE_SHFL(8, a); STAGE_SHFL(4, a);
      STAGE_SHFL(2, a); STAGE_SHFL(1, a); LOCAL3(a); }
    { STAGE_SHFL(16, true); STAGE_SHFL(8, true); STAGE_SHFL(4, true);
      STAGE_SHFL(2, true); STAGE_SHFL(1, true); LOCAL3(true); }

    #undef CE
    #undef STAGE_SHFL
    #undef LOCAL3

    // rank of element in key[i] is 8*lane + i; valid ranks are [0, vl)
    {
        const float rinv = refined_rcp((float)vl);        // r1(vl)
        #pragma unroll
        for (int i = 0; i < 8; i++) {
            int r = lane * 8 + i;
            if (r < vl) {
                float q  = __fmul_rn((float)r, rinv);     // == div.full(r,vl)
                float rb = __fmul_rn(q, 65.0f);
                int bi = (int)rb;                         // trunc
                bi = bi > (NB - 1) ? (NB - 1) : bi;
                sbin[w][key[i] & 0xffu] = (unsigned char)bi;
            }
        }
    }
    __syncwarp();        // sbin + hist-zero visible within warp
    __syncthreads();     // zero-filled output visible to all (before STGs)

    // ---- Phase 2 (warp-local): codes, match-dedup u8 hist, scatter store --
    int code[8];
    {
        const uint2 bw = *(const uint2*)&sbin[w][lane * 8];
        const unsigned int b8 = sbin[w][lane * 8 + 8];    // padded row, safe
        const int bl[8] = {
            (int)( bw.x        & 0xffu), (int)((bw.x >>  8) & 0xffu),
            (int)((bw.x >> 16) & 0xffu), (int)((bw.x >> 24) & 0xffu),
            (int)( bw.y        & 0xffu), (int)((bw.y >>  8) & 0xffu),
            (int)((bw.y >> 16) & 0xffu), (int)((bw.y >> 24) & 0xffu)
        };
        #pragma unroll
        for (int i = 0; i < 8; i++) {
            int tt = lane * 8 + i;
            bool tr = (tt >= first) && (tt < last);       // both ends valid
            int nb = (i < 7) ? bl[i + 1] : (int)b8;
            code[i] = tr ? (bl[i] * NB + nb) : SENT;
        }
    }

    // histogram with intra-warp dedup: leader of each equal-code group does
    // a single read-modify-write. No atomics -> deterministic & exact.
    #pragma unroll
    for (int i = 0; i < 8; i++) {
        unsigned int mask = __match_any_sync(0xffffffffu, code[i]);
        int cnt = __popc(mask);
        int leader = __ffs(mask) - 1;
        if (lane == leader && code[i] != SENT) {
            shist[w][code[i]] = (unsigned char)(shist[w][code[i]] + cnt);
        }
        __syncwarp();
    }
    __syncwarp();

    // scatter-store touched bins: value rn(count * r1(norm)) == div.full.
    // lanes sharing a code store identical bits -> benign deterministic race.
    {
        int nrm = vl - 1; if (nrm < 1) nrm = 1;
        const float rnorm = refined_rcp((float)nrm);
        float* orow = out + (size_t)rowg * NB2;
        #pragma unroll
        for (int i = 0; i < 8; i++) {
            if (code[i] != SENT) {
                unsigned int c = (unsigned int)shist[w][code[i]];
                orow[code[i]] = __fmul_rn((float)c, rnorm);
            }
        }
    }
}

extern "C" void kernel_launch(void* const* d_in, const int* in_sizes, int n_in,
                              void* d_out, int out_size)
{
    const float* x = (const float*)d_in[0];
    float* out = (float*)d_out;
    const int nrows = in_sizes[0] / L;       // N*C = 16384 (divisible by 8)
    mtf_kernel<<<nrows / RPC, 256>>>(x, out);
}

// round 9
// speedup vs baseline: 1.8121x; 1.8121x over previous
#include <cuda_runtime.h>
#include <cstdint>

// MTF_68461778698457: Markov Transition Field
// x: (N=4096, C=4, L=256) f32  ->  out: (N, C, 65, 65) f32
//
// One WARP per row (8 elems/thread register bitonic sort), 8 rows per CTA.
// Phase 2 warp-local: u8 histogram with match_any dedup (no atomics),
// then a single fully-coalesced float4 stream of the whole 4225-entry row
// (funnel-shift handles the (row*4225)%4 alignment phase). Every output
// byte written exactly once.
//
// Numerics (locked, rel_err == 0.0): reference division == classical
// div.full.f32 Newton expansion; we hoist the refined reciprocal r1(b) and
// mul.rn — bit-identical to div.full(a,b).  rn(0 * r1) = +0.0 == ref.

constexpr int L    = 256;
constexpr int NB   = 65;
constexpr int NB2  = NB * NB;        // 4225
constexpr int RPC  = 8;              // rows per CTA (one per warp)
constexpr int HPAD = 4352;           // u8 hist row, 16B multiple, > 4225+4
constexpr int SENT = 4300;           // sentinel code for invalid transitions

__device__ __forceinline__ float refined_rcp(float b)
{
    float r;
    asm("{\n\t"
        ".reg .f32 r0, e;\n\t"
        "rcp.approx.f32 r0, %1;\n\t"
        "fma.rn.f32 e, %1, r0, 0fBF800000;\n\t"   // e' = b*r0 - 1
        "neg.f32 e, e;\n\t"                        // e  = 1 - b*r0
        "fma.rn.f32 %0, r0, e, r0;\n\t"            // r1 = r0 + r0*e
        "}"
        : "=f"(r) : "f"(b));
    return r;
}

__global__ __launch_bounds__(256)
void mtf_kernel(const float* __restrict__ x, float* __restrict__ out)
{
    __shared__ __align__(16) unsigned char shist[RPC][HPAD];  // 34.8 KB
    __shared__ __align__(16) unsigned char sbin[RPC][272];    //  2.2 KB

    const int t    = threadIdx.x;
    const int w    = t >> 5;
    const int lane = t & 31;
    const long long rowg = (long long)blockIdx.x * RPC + w;

    // ---- zero this warp's u8 histogram (warp-private) ---------------------
    {
        uint4* h4 = (uint4*)shist[w];
        const uint4 z = make_uint4(0u, 0u, 0u, 0u);
        #pragma unroll
        for (int i = lane; i < HPAD / 16; i += 32) h4[i] = z;
    }

    // ---- Phase 1: load, range scan, register bitonic sort ------------------
    const float* xr = x + rowg * L + lane * 8;
    float4 va = *(const float4*)(xr);
    float4 vb = *(const float4*)(xr + 4);
    float v[8] = { va.x, va.y, va.z, va.w, vb.x, vb.y, vb.z, vb.w };

    int locF = 256, locE = -1;
    #pragma unroll
    for (int i = 0; i < 8; i++) {
        int idx = lane * 8 + i;
        if (v[i] != 0.0f) {
            if (idx < locF) locF = idx;
            if (idx > locE) locE = idx;
        }
    }
    const int first = __reduce_min_sync(0xffffffffu, locF);
    const int last  = __reduce_max_sync(0xffffffffu, locE);
    const bool has  = (last >= first);
    const int  vl   = has ? (last - first + 1) : 1;

    unsigned long long key[8];
    #pragma unroll
    for (int i = 0; i < 8; i++) {
        int idx = lane * 8 + i;
        unsigned int u = __float_as_uint(v[i]);
        unsigned int o = (u & 0x80000000u) ? ~u : (u | 0x80000000u);
        bool valid = has && (idx >= first) && (idx <= last);
        key[i] = valid ? ((((unsigned long long)o) << 32) | (unsigned)idx)
                       : 0xFFFFFFFFFFFFFFFFull;
    }

    #define CE(a, b, asc)                                                    \
        do {                                                                 \
            if ((key[a] > key[b]) == (asc)) {                                \
                unsigned long long _tmp = key[a];                            \
                key[a] = key[b]; key[b] = _tmp;                              \
            }                                                                \
        } while (0)

    #define STAGE_SHFL(off, asc)                                             \
        do {                                                                 \
            bool _lower = (lane & (off)) == 0;                               \
            bool _keepMin = ((asc) == _lower);                               \
            _Pragma("unroll")                                                \
            for (int _i = 0; _i < 8; _i++) {                                 \
                unsigned long long _o =                                      \
                    __shfl_xor_sync(0xffffffffu, key[_i], (off));            \
                bool _take = (_o < key[_i]) == _keepMin;                     \
                key[_i] = _take ? _o : key[_i];                              \
            }                                                                \
        } while (0)

    #define LOCAL3(asc)                                                      \
        do {                                                                 \
            CE(0,4,asc); CE(1,5,asc); CE(2,6,asc); CE(3,7,asc);              \
            CE(0,2,asc); CE(1,3,asc); CE(4,6,asc); CE(5,7,asc);              \
            CE(0,1,asc); CE(2,3,asc); CE(4,5,asc); CE(6,7,asc);              \
        } while (0)

    CE(0,1,true); CE(2,3,false); CE(4,5,true); CE(6,7,false);
    CE(0,2,true); CE(1,3,true);  CE(4,6,false); CE(5,7,false);
    CE(0,1,true); CE(2,3,true);  CE(4,5,false); CE(6,7,false);
    { bool a = (lane & 1) == 0; LOCAL3(a); }
    { bool a = (lane & 2) == 0; STAGE_SHFL(1, a); LOCAL3(a); }
    { bool a = (lane & 4) == 0; STAGE_SHFL(2, a); STAGE_SHFL(1, a); LOCAL3(a); }
    { bool a = (lane & 8) == 0; STAGE_SHFL(4, a); STAGE_SHFL(2, a);
      STAGE_SHFL(1, a); LOCAL3(a); }
    { bool a = (lane & 16) == 0; STAGE_SHFL(8, a); STAGE_SHFL(4, a);
      STAGE_SHFL(2, a); STAGE_SHFL(1, a); LOCAL3(a); }
    { STAGE_SHFL(16, true); STAGE_SHFL(8, true); STAGE_SHFL(4, true);
      STAGE_SHFL(2, true); STAGE_SHFL(1, true); LOCAL3(true); }

    #undef CE
    #undef STAGE_SHFL
    #undef LOCAL3

    // rank of element in key[i] is 8*lane + i; valid ranks are [0, vl)
    {
        const float rinv = refined_rcp((float)vl);        // r1(vl)
        #pragma unroll
        for (int i = 0; i < 8; i++) {
            int r = lane * 8 + i;
            if (r < vl) {
                float q  = __fmul_rn((float)r, rinv);     // == div.full(r,vl)
                float rb = __fmul_rn(q, 65.0f);
                int bi = (int)rb;                         // trunc
                bi = bi > (NB - 1) ? (NB - 1) : bi;
                sbin[w][key[i] & 0xffu] = (unsigned char)bi;
            }
        }
    }
    __syncwarp();        // sbin + zeroed hist visible within warp

    // ---- Phase 2 (warp-local): codes, match-dedup u8 hist -----------------
    int code[8];
    {
        const uint2 bw = *(const uint2*)&sbin[w][lane * 8];
        const unsigned int b8 = sbin[w][lane * 8 + 8];    // padded row, safe
        const int bl[8] = {
            (int)( bw.x        & 0xffu), (int)((bw.x >>  8) & 0xffu),
            (int)((bw.x >> 16) & 0xffu), (int)((bw.x >> 24) & 0xffu),
            (int)( bw.y        & 0xffu), (int)((bw.y >>  8) & 0xffu),
            (int)((bw.y >> 16) & 0xffu), (int)((bw.y >> 24) & 0xffu)
        };
        #pragma unroll
        for (int i = 0; i < 8; i++) {
            int tt = lane * 8 + i;
            bool tr = (tt >= first) && (tt < last);       // both ends valid
            int nb = (i < 7) ? bl[i + 1] : (int)b8;
            code[i] = tr ? (bl[i] * NB + nb) : SENT;
        }
    }

    #pragma unroll
    for (int i = 0; i < 8; i++) {
        unsigned int mask = __match_any_sync(0xffffffffu, code[i]);
        int cnt = __popc(mask);
        int leader = __ffs(mask) - 1;
        if (lane == leader && code[i] != SENT) {
            shist[w][code[i]] = (unsigned char)(shist[w][code[i]] + cnt);
        }
        __syncwarp();
    }

    // ---- Stream the full row out, coalesced float4, single write ----------
    {
        int nrm = vl - 1; if (nrm < 1) nrm = 1;
        const float rnorm = refined_rcp((float)nrm);      // r1(norm)
        const size_t p0 = (size_t)rowg * NB2;
        float* op = out + p0;
        const int lead = (int)((4 - (p0 & 3)) & 3);       // floats to peel
        const int rem  = NB2 - lead;
        const int nv   = rem >> 2;                        // float4 count
        const int tail = rem & 3;
        const unsigned int* hw = (const unsigned int*)shist[w];
        const int sh = 8 * lead;

        if (lane < lead)
            op[lane] = __fmul_rn((float)shist[w][lane], rnorm);

        for (int i = lane; i < nv; i += 32) {
            // bytes [lead+4i, lead+4i+4) = funnel(hw[i], hw[i+1], 8*lead)
            unsigned int lo = hw[i];
            unsigned int hi = hw[i + 1];                  // HPAD pad: in-bounds
            unsigned int c4 = (sh == 0) ? lo : __funnelshift_r(lo, hi, sh);
            float4 wv;
            wv.x = __fmul_rn((float)( c4        & 0xffu), rnorm);
            wv.y = __fmul_rn((float)((c4 >>  8) & 0xffu), rnorm);
            wv.z = __fmul_rn((float)((c4 >> 16) & 0xffu), rnorm);
            wv.w = __fmul_rn((float)((c4 >> 24)        ), rnorm);
            *(float4*)(op + lead + 4 * i) = wv;
        }
        if (lane < tail) {
            int f = lead + 4 * nv + lane;
            op[f] = __fmul_rn((float)shist[w][f], rnorm);
        }
    }
}

extern "C" void kernel_launch(void* const* d_in, const int* in_sizes, int n_in,
                              void* d_out, int out_size)
{
    const float* x = (const float*)d_in[0];
    float* out = (float*)d_out;
    const int nrows = in_sizes[0] / L;       // N*C = 16384 (divisible by 8)
    mtf_kernel<<<nrows / RPC, 256>>>(x, out);
}

// round 10
// speedup vs baseline: 1.8300x; 1.0099x over previous
#include <cuda_runtime.h>
#include <cstdint>

// MTF_68461778698457: Markov Transition Field
// x: (N=4096, C=4, L=256) f32  ->  out: (N, C, 65, 65) f32
//
// One WARP per row (8 elems/thread register bitonic sort), 8 rows per CTA.
// Phase 2 warp-local: u8 histogram with match_any dedup (no atomics),
// then a single fully-coalesced float4 stream of the 4225-entry row.
// u8->f32 conversion via PRMT+FADD bias trick (exact for c<=255) to avoid
// quarter-rate I2F on the conversion pipe.
//
// Numerics (locked, rel_err == 0.0): reference division == classical
// div.full.f32 Newton expansion; we hoist the refined reciprocal r1(b) and
// mul.rn — bit-identical to div.full(a,b).  rn(0 * r1) = +0.0 == ref.

constexpr int L    = 256;
constexpr int NB   = 65;
constexpr int NB2  = NB * NB;        // 4225
constexpr int RPC  = 8;              // rows per CTA (one per warp)
constexpr int HPAD = 4352;           // u8 hist row, 16B multiple, > 4225+4
constexpr int SENT = 4300;           // sentinel code for invalid transitions

__device__ __forceinline__ float refined_rcp(float b)
{
    float r;
    asm("{\n\t"
        ".reg .f32 r0, e;\n\t"
        "rcp.approx.f32 r0, %1;\n\t"
        "fma.rn.f32 e, %1, r0, 0fBF800000;\n\t"   // e' = b*r0 - 1
        "neg.f32 e, e;\n\t"                        // e  = 1 - b*r0
        "fma.rn.f32 %0, r0, e, r0;\n\t"            // r1 = r0 + r0*e
        "}"
        : "=f"(r) : "f"(b));
    return r;
}

// Exact u8 -> f32 without I2F: bits(2^23 + c) == 0x4B000000 | c for c<256.
__device__ __forceinline__ float u8_to_f32(unsigned int packed, int sel)
{
    unsigned int b = __byte_perm(packed, 0x4B000000u, 0x7540 + sel);
    return __uint_as_float(b) - 8388608.0f;    // exact (float)c
}

__global__ __launch_bounds__(256)
void mtf_kernel(const float* __restrict__ x, float* __restrict__ out)
{
    __shared__ __align__(16) unsigned char shist[RPC][HPAD];  // 34.8 KB
    __shared__ __align__(16) unsigned char sbin[RPC][272];    //  2.2 KB

    const int t    = threadIdx.x;
    const int w    = t >> 5;
    const int lane = t & 31;
    const long long rowg = (long long)blockIdx.x * RPC + w;

    // ---- zero this warp's u8 histogram (warp-private) ---------------------
    {
        uint4* h4 = (uint4*)shist[w];
        const uint4 z = make_uint4(0u, 0u, 0u, 0u);
        #pragma unroll
        for (int i = lane; i < HPAD / 16; i += 32) h4[i] = z;
    }

    // ---- Phase 1: load, range scan, register bitonic sort ------------------
    const float* xr = x + rowg * L + lane * 8;
    float4 va = *(const float4*)(xr);
    float4 vb = *(const float4*)(xr + 4);
    float v[8] = { va.x, va.y, va.z, va.w, vb.x, vb.y, vb.z, vb.w };

    int locF = 256, locE = -1;
    #pragma unroll
    for (int i = 0; i < 8; i++) {
        int idx = lane * 8 + i;
        if (v[i] != 0.0f) {
            if (idx < locF) locF = idx;
            if (idx > locE) locE = idx;
        }
    }
    const int first = __reduce_min_sync(0xffffffffu, locF);
    const int last  = __reduce_max_sync(0xffffffffu, locE);
    const bool has  = (last >= first);
    const int  vl   = has ? (last - first + 1) : 1;

    unsigned long long key[8];
    #pragma unroll
    for (int i = 0; i < 8; i++) {
        int idx = lane * 8 + i;
        unsigned int u = __float_as_uint(v[i]);
        unsigned int o = (u & 0x80000000u) ? ~u : (u | 0x80000000u);
        bool valid = has && (idx >= first) && (idx <= last);
        key[i] = valid ? ((((unsigned long long)o) << 32) | (unsigned)idx)
                       : 0xFFFFFFFFFFFFFFFFull;
    }

    #define CE(a, b, asc)                                                    \
        do {                                                                 \
            if ((key[a] > key[b]) == (asc)) {                                \
                unsigned long long _tmp = key[a];                            \
                key[a] = key[b]; key[b] = _tmp;                              \
            }                                                                \
        } while (0)

    #define STAGE_SHFL(off, asc)                                             \
        do {                                                                 \
            bool _lower = (lane & (off)) == 0;                               \
            bool _keepMin = ((asc) == _lower);                               \
            _Pragma("unroll")                                                \
            for (int _i = 0; _i < 8; _i++) {                                 \
                unsigned long long _o =                                      \
                    __shfl_xor_sync(0xffffffffu, key[_i], (off));            \
                bool _take = (_o < key[_i]) == _keepMin;                     \
                key[_i] = _take ? _o : key[_i];                              \
            }                                                                \
        } while (0)

    #define LOCAL3(asc)                                                      \
        do {                                                                 \
            CE(0,4,asc); CE(1,5,asc); CE(2,6,asc); CE(3,7,asc);              \
            CE(0,2,asc); CE(1,3,asc); CE(4,6,asc); CE(5,7,asc);              \
            CE(0,1,asc); CE(2,3,asc); CE(4,5,asc); CE(6,7,asc);              \
        } while (0)

    CE(0,1,true); CE(2,3,false); CE(4,5,true); CE(6,7,false);
    CE(0,2,true); CE(1,3,true);  CE(4,6,false); CE(5,7,false);
    CE(0,1,true); CE(2,3,true);  CE(4,5,false); CE(6,7,false);
    { bool a = (lane & 1) == 0; LOCAL3(a); }
    { bool a = (lane & 2) == 0; STAGE_SHFL(1, a); LOCAL3(a); }
    { bool a = (lane & 4) == 0; STAGE_SHFL(2, a); STAGE_SHFL(1, a); LOCAL3(a); }
    { bool a = (lane & 8) == 0; STAGE_SHFL(4, a); STAGE_SHFL(2, a);
      STAGE_SHFL(1, a); LOCAL3(a); }
    { bool a = (lane & 16) == 0; STAGE_SHFL(8, a); STAGE_SHFL(4, a);
      STAGE_SHFL(2, a); STAGE_SHFL(1, a); LOCAL3(a); }
    { STAGE_SHFL(16, true); STAGE_SHFL(8, true); STAGE_SHFL(4, true);
      STAGE_SHFL(2, true); STAGE_SHFL(1, true); LOCAL3(true); }

    #undef CE
    #undef STAGE_SHFL
    #undef LOCAL3

    // rank of element in key[i] is 8*lane + i; valid ranks are [0, vl)
    {
        const float rinv = refined_rcp((float)vl);        // r1(vl)
        const float base = (float)(lane * 8);             // one I2F
        #pragma unroll
        for (int i = 0; i < 8; i++) {
            int r = lane * 8 + i;
            if (r < vl) {
                float fr = base + (float)i;               // exact FADD (<256)
                float q  = __fmul_rn(fr, rinv);           // == div.full(r,vl)
                float rb = __fmul_rn(q, 65.0f);
                int bi = (int)rb;                         // trunc
                bi = bi > (NB - 1) ? (NB - 1) : bi;
                sbin[w][key[i] & 0xffu] = (unsigned char)bi;
            }
        }
    }
    __syncwarp();        // sbin + zeroed hist visible within warp

    // ---- Phase 2 (warp-local): codes, match-dedup u8 hist -----------------
    int code[8];
    {
        const uint2 bw = *(const uint2*)&sbin[w][lane * 8];
        const unsigned int b8 = sbin[w][lane * 8 + 8];    // padded row, safe
        const int bl[8] = {
            (int)( bw.x        & 0xffu), (int)((bw.x >>  8) & 0xffu),
            (int)((bw.x >> 16) & 0xffu), (int)((bw.x >> 24) & 0xffu),
            (int)( bw.y        & 0xffu), (int)((bw.y >>  8) & 0xffu),
            (int)((bw.y >> 16) & 0xffu), (int)((bw.y >> 24) & 0xffu)
        };
        #pragma unroll
        for (int i = 0; i < 8; i++) {
            int tt = lane * 8 + i;
            bool tr = (tt >= first) && (tt < last);       // both ends valid
            int nb = (i < 7) ? bl[i + 1] : (int)b8;
            code[i] = tr ? (bl[i] * NB + nb) : SENT;
        }
    }

    #pragma unroll
    for (int i = 0; i < 8; i++) {
        unsigned int mask = __match_any_sync(0xffffffffu, code[i]);
        int cnt = __popc(mask);
        int leader = __ffs(mask) - 1;
        if (lane == leader && code[i] != SENT) {
            shist[w][code[i]] = (unsigned char)(shist[w][code[i]] + cnt);
        }
        __syncwarp();
    }

    // ---- Stream the full row out, coalesced float4, single write ----------
    {
        int nrm = vl - 1; if (nrm < 1) nrm = 1;
        const float rnorm = refined_rcp((float)nrm);      // r1(norm)
        const size_t p0 = (size_t)rowg * NB2;
        float* op = out + p0;
        const int lead = (int)((4 - (p0 & 3)) & 3);       // floats to peel
        const int rem  = NB2 - lead;
        const int nv   = rem >> 2;                        // float4 count
        const int tail = rem & 3;
        const unsigned int* hw = (const unsigned int*)shist[w];
        const int sh = 8 * lead;

        if (lane < lead)
            op[lane] = __fmul_rn((float)shist[w][lane], rnorm);

        for (int i = lane; i < nv; i += 32) {
            unsigned int lo = hw[i];
            unsigned int hi = hw[i + 1];                  // HPAD pad: in-bounds
            unsigned int c4 = (sh == 0) ? lo : __funnelshift_r(lo, hi, sh);
            float4 wv;
            wv.x = __fmul_rn(u8_to_f32(c4, 0), rnorm);
            wv.y = __fmul_rn(u8_to_f32(c4, 1), rnorm);
            wv.z = __fmul_rn(u8_to_f32(c4, 2), rnorm);
            wv.w = __fmul_rn(u8_to_f32(c4, 3), rnorm);
            *(float4*)(op + lead + 4 * i) = wv;
        }
        if (lane < tail) {
            int f = lead + 4 * nv + lane;
            op[f] = __fmul_rn((float)shist[w][f], rnorm);
        }
    }
}

extern "C" void kernel_launch(void* const* d_in, const int* in_sizes, int n_in,
                              void* d_out, int out_size)
{
    const float* x = (const float*)d_in[0];
    float* out = (float*)d_out;
    const int nrows = in_sizes[0] / L;       // N*C = 16384 (divisible by 8)
    mtf_kernel<<<nrows / RPC, 256>>>(x, out);
}